// round 3
// baseline (speedup 1.0000x reference)
#include <cuda_runtime.h>

#define B_   4
#define CIN  128
#define COUT 128
#define H_   128
#define W_   128
#define G_   4
#define CG   32
#define KK   9
#define HW   (H_*W_)
#define NOFF 72   // G*KK*2

// ---- scratch (device globals; no allocations allowed) ----
__device__ float g_off[B_*NOFF*HW];        // 18 MB: offset map [b][o][h][w]
__device__ float g_wT[G_*KK*CG*COUT];      // 576 KB: weights [g][kk][c][co]

// ============================================================
// Kernel 1: transpose deform weights to [g][kk][c][co]
// ============================================================
__global__ void prep_w(const float* __restrict__ w_def) {
    int i = blockIdx.x * 256 + threadIdx.x;     // i = ((g*9+kk)*32+c)*128+co
    if (i >= G_*KK*CG*COUT) return;
    int co = i & 127;
    int c  = (i >> 7) & 31;
    int gk = i >> 12;           // g*9+kk
    int kk = gk % 9;
    int g  = gk / 9;
    g_wT[i] = w_def[(co*CIN + g*CG + c)*KK + kk];
}

// ============================================================
// Kernel 2: 1x1 offset conv  (GEMM 65536 x 72 x 128 + bias)
// block: 256 thr, tile = 32 pixels (one row segment), all 72 outputs
// ============================================================
__global__ __launch_bounds__(256) void off_kernel(
        const float* __restrict__ x,
        const float* __restrict__ w_off,
        const float* __restrict__ b_off) {
    __shared__ __align__(16) float xs[32][132];   // [px][c], padded
    __shared__ __align__(16) float ws[NOFF][32];  // w chunk [o][c']

    int b  = blockIdx.z;
    int h  = blockIdx.y;
    int w0 = blockIdx.x * 32;
    int t  = threadIdx.x;
    int lane = t & 31, wid = t >> 5;

    // stage x tile, transposed: xs[px][c] <- x[b][c][h][w0+px]
    const float* xp = x + (size_t)b*CIN*HW + h*W_ + w0;
    for (int i = t; i < 128*32; i += 256) {
        int c = i >> 5, px = i & 31;
        xs[px][c] = xp[(size_t)c*HW + px];
    }

    float acc[9];
    #pragma unroll
    for (int j = 0; j < 9; j++) acc[j] = 0.f;
    int obase = wid * 9;     // each warp owns 9 output channels

    for (int cc = 0; cc < 4; cc++) {          // 4 chunks of 32 channels
        __syncthreads();
        // stage w chunk: ws[o][c'] <- w_off[o][cc*32+c']
        for (int i = t; i < NOFF*32; i += 256) {
            int o = i >> 5, c2 = i & 31;
            ws[o][c2] = w_off[o*CIN + cc*32 + c2];
        }
        __syncthreads();
        #pragma unroll
        for (int c2 = 0; c2 < 32; c2 += 4) {
            float4 xv = *(const float4*)&xs[lane][cc*32 + c2];
            #pragma unroll
            for (int j = 0; j < 9; j++) {
                float4 wq = *(const float4*)&ws[obase + j][c2];
                acc[j] += xv.x*wq.x + xv.y*wq.y + xv.z*wq.z + xv.w*wq.w;
            }
        }
    }

    float* op = g_off + (size_t)b*NOFF*HW + h*W_ + w0 + lane;
    #pragma unroll
    for (int j = 0; j < 9; j++)
        op[(size_t)(obase + j)*HW] = acc[j] + b_off[obase + j];
}

// ============================================================
// Kernel 3: deformable conv + ReLU
// block: 128 thr, tile = 32 pixels x 128 couts
// ============================================================
__global__ __launch_bounds__(128, 8) void main_kernel(
        const float* __restrict__ x,
        float* __restrict__ out) {
    __shared__ __align__(16) float s[32][36];     // sampled vals [c][px]
    __shared__ __align__(16) float ws[4224];      // w slice [c][co] (4096) / epi [128][33]

    int b  = blockIdx.z;
    int h  = blockIdx.y;
    int w0 = blockIdx.x * 32;
    int t  = threadIdx.x;
    int lane = t & 31, wid = t >> 5;

    float acc[4][8];
    #pragma unroll
    for (int i = 0; i < 4; i++)
        #pragma unroll
        for (int j = 0; j < 8; j++) acc[i][j] = 0.f;

    const float* xb   = x + (size_t)b*CIN*HW;
    const float* offp = g_off + (size_t)b*NOFF*HW + h*W_ + w0 + lane;

    int co4 = lane * 4;   // compute-phase: 4 consecutive couts
    int px8 = wid * 8;    // compute-phase: 8 consecutive pixels

    for (int g = 0; g < G_; g++) {
        const float* xg = xb + (size_t)g*CG*HW;
        for (int kk = 0; kk < KK; kk++) {
            __syncthreads();   // protect smem from previous compute reads

            // ---- stage weight slice [c][co] (coalesced float4) ----
            const float4* wtp = (const float4*)(g_wT + (size_t)(g*9 + kk)*CG*COUT);
            float4* wsd = (float4*)ws;
            #pragma unroll
            for (int i = 0; i < 8; i++) wsd[t + i*128] = wtp[t + i*128];

            // ---- per-pixel sampling params (px = lane) ----
            float offy = offp[(size_t)((g*9 + kk)*2 + 0)*HW];
            float offx = offp[(size_t)((g*9 + kk)*2 + 1)*HW];
            int ky = kk / 3, kx = kk % 3;
            float py  = offy + (float)(ky - 1) + (float)h;
            float pxf = offx + (float)(kx - 1) + (float)(w0 + lane);
            float y0f = floorf(py), x0f = floorf(pxf);
            float wy1 = py - y0f, wx1 = pxf - x0f;
            float wy0 = 1.f - wy1, wx0 = 1.f - wx1;
            int y0 = (int)y0f, x0 = (int)x0f;
            int y1 = y0 + 1,  x1 = x0 + 1;
            bool vy0 = (y0 >= 0) & (y0 < H_);
            bool vy1 = (y1 >= 0) & (y1 < H_);
            bool vx0 = (x0 >= 0) & (x0 < W_);
            bool vx1 = (x1 >= 0) & (x1 < W_);
            float c00 = (vy0 & vx0) ? wy0*wx0 : 0.f;
            float c01 = (vy0 & vx1) ? wy0*wx1 : 0.f;
            float c10 = (vy1 & vx0) ? wy1*wx0 : 0.f;
            float c11 = (vy1 & vx1) ? wy1*wx1 : 0.f;
            int iy0 = min(max(y0, 0), H_-1), iy1 = min(max(y1, 0), H_-1);
            int ix0 = min(max(x0, 0), W_-1), ix1 = min(max(x1, 0), W_-1);
            int i00 = iy0*W_ + ix0, i01 = iy0*W_ + ix1;
            int i10 = iy1*W_ + ix0, i11 = iy1*W_ + ix1;

            // ---- bilinear gather: thread does 8 channel rows of s ----
            #pragma unroll
            for (int j = 0; j < 8; j++) {
                const float* xc = xg + (size_t)(wid + 4*j)*HW;
                float v = c00*xc[i00] + c01*xc[i01] + c10*xc[i10] + c11*xc[i11];
                s[wid + 4*j][lane] = v;
            }
            __syncthreads();

            // ---- micro-GEMM: acc[4co][8px] += w[c][co] * s[c][px] ----
            #pragma unroll 8
            for (int c = 0; c < CG; c++) {
                float4 wq = *(const float4*)&ws[c*128 + co4];
                float4 sa = *(const float4*)&s[c][px8];
                float4 sb = *(const float4*)&s[c][px8 + 4];
                acc[0][0] += wq.x*sa.x; acc[0][1] += wq.x*sa.y;
                acc[0][2] += wq.x*sa.z; acc[0][3] += wq.x*sa.w;
                acc[0][4] += wq.x*sb.x; acc[0][5] += wq.x*sb.y;
                acc[0][6] += wq.x*sb.z; acc[0][7] += wq.x*sb.w;
                acc[1][0] += wq.y*sa.x; acc[1][1] += wq.y*sa.y;
                acc[1][2] += wq.y*sa.z; acc[1][3] += wq.y*sa.w;
                acc[1][4] += wq.y*sb.x; acc[1][5] += wq.y*sb.y;
                acc[1][6] += wq.y*sb.z; acc[1][7] += wq.y*sb.w;
                acc[2][0] += wq.z*sa.x; acc[2][1] += wq.z*sa.y;
                acc[2][2] += wq.z*sa.z; acc[2][3] += wq.z*sa.w;
                acc[2][4] += wq.z*sb.x; acc[2][5] += wq.z*sb.y;
                acc[2][6] += wq.z*sb.z; acc[2][7] += wq.z*sb.w;
                acc[3][0] += wq.w*sa.x; acc[3][1] += wq.w*sa.y;
                acc[3][2] += wq.w*sa.z; acc[3][3] += wq.w*sa.w;
                acc[3][4] += wq.w*sb.x; acc[3][5] += wq.w*sb.y;
                acc[3][6] += wq.w*sb.z; acc[3][7] += wq.w*sb.w;
            }
        }
    }

    // ---- epilogue: transpose via smem, ReLU, coalesced NCHW store ----
    __syncthreads();
    float* s2 = ws;   // reuse as [128][33]
    #pragma unroll
    for (int i = 0; i < 4; i++)
        #pragma unroll
        for (int j = 0; j < 8; j++) {
            float v = acc[i][j];
            s2[(co4 + i)*33 + (px8 + j)] = v > 0.f ? v : 0.f;
        }
    __syncthreads();
    float* outp = out + (size_t)b*COUT*HW + h*W_ + w0;
    #pragma unroll
    for (int k = 0; k < 32; k++) {
        int row = wid*32 + k;
        outp[(size_t)row*HW + lane] = s2[row*33 + lane];
    }
}

// ============================================================
extern "C" void kernel_launch(void* const* d_in, const int* in_sizes, int n_in,
                              void* d_out, int out_size) {
    const float* x     = (const float*)d_in[0];
    const float* w_off = (const float*)d_in[1];
    const float* b_off = (const float*)d_in[2];
    const float* w_def = (const float*)d_in[3];
    float* out = (float*)d_out;

    prep_w<<<576, 256>>>(w_def);
    off_kernel<<<dim3(W_/32, H_, B_), 256>>>(x, w_off, b_off);
    main_kernel<<<dim3(W_/32, H_, B_), 128>>>(x, out);
}

// round 5
// speedup vs baseline: 1.0206x; 1.0206x over previous
#include <cuda_runtime.h>

#define B_   4
#define CIN  128
#define COUT 128
#define H_   128
#define W_   128
#define G_   4
#define CG   32
#define KK   9
#define HW   (H_*W_)
#define NOFF 72   // G*KK*2

// ---- scratch (device globals; no allocations allowed) ----
__device__ float g_off[B_*NOFF*HW];        // 18 MB: offset map [b][o][h][w]
__device__ float g_wT[G_*KK*CG*COUT];      // 576 KB: weights [g][kk][c][co]

// ---- packed f32x2 helpers (2x fp32 FMA throughput on sm_103a) ----
__device__ __forceinline__ void ffma2(unsigned long long& d,
                                      unsigned long long a,
                                      unsigned long long b) {
    asm("fma.rn.f32x2 %0, %1, %2, %0;" : "+l"(d) : "l"(a), "l"(b));
}
__device__ __forceinline__ unsigned long long pack2(float v) {
    unsigned long long r;
    asm("mov.b64 %0, {%1, %1};" : "=l"(r) : "f"(v));
    return r;
}
__device__ __forceinline__ void unpack2(float& lo, float& hi, unsigned long long v) {
    asm("mov.b64 {%0, %1}, %2;" : "=f"(lo), "=f"(hi) : "l"(v));
}

// ============================================================
// Kernel 1: transpose deform weights to [g][kk][c][co]
// ============================================================
__global__ void prep_w(const float* __restrict__ w_def) {
    int i = blockIdx.x * 256 + threadIdx.x;     // i = ((g*9+kk)*32+c)*128+co
    if (i >= G_*KK*CG*COUT) return;
    int co = i & 127;
    int c  = (i >> 7) & 31;
    int gk = i >> 12;           // g*9+kk
    int kk = gk % 9;
    int g  = gk / 9;
    g_wT[i] = w_def[(co*CIN + g*CG + c)*KK + kk];
}

// ============================================================
// Kernel 2: 1x1 offset conv  (GEMM 65536 x 72 x 128 + bias)
// block: 256 thr, tile = 32 pixels (one row segment), all 72 outputs
// packed f32x2 along the reduction dim, horizontal add at the end
// ============================================================
__global__ __launch_bounds__(256) void off_kernel(
        const float* __restrict__ x,
        const float* __restrict__ w_off,
        const float* __restrict__ b_off) {
    __shared__ __align__(16) float xs[32][138];   // [px][c], stride 138 (2-way max for u64)
    __shared__ __align__(16) float ws[NOFF][32];  // w chunk [o][c']

    int b  = blockIdx.z;
    int h  = blockIdx.y;
    int w0 = blockIdx.x * 32;
    int t  = threadIdx.x;
    int lane = t & 31, wid = t >> 5;

    // stage x tile, transposed: xs[px][c] <- x[b][c][h][w0+px]
    const float* xp = x + (size_t)b*CIN*HW + h*W_ + w0;
    for (int i = t; i < 128*32; i += 256) {
        int c = i >> 5, px = i & 31;
        xs[px][c] = xp[(size_t)c*HW + px];
    }

    unsigned long long acc2[9];
    #pragma unroll
    for (int j = 0; j < 9; j++) acc2[j] = 0ULL;
    int obase = wid * 9;     // each warp owns 9 output channels

    for (int cc = 0; cc < 4; cc++) {          // 4 chunks of 32 channels
        __syncthreads();
        // stage w chunk: ws[o][c'] <- w_off[o][cc*32+c']
        for (int i = t; i < NOFF*32; i += 256) {
            int o = i >> 5, c2 = i & 31;
            ws[o][c2] = w_off[o*CIN + cc*32 + c2];
        }
        __syncthreads();
        #pragma unroll
        for (int c2 = 0; c2 < 32; c2 += 2) {
            unsigned long long xv = *(const unsigned long long*)&xs[lane][cc*32 + c2];
            #pragma unroll
            for (int j = 0; j < 9; j++) {
                unsigned long long wv = *(const unsigned long long*)&ws[obase + j][c2];
                ffma2(acc2[j], xv, wv);
            }
        }
    }

    float* op = g_off + (size_t)b*NOFF*HW + h*W_ + w0 + lane;
    #pragma unroll
    for (int j = 0; j < 9; j++) {
        float lo, hi;
        unpack2(lo, hi, acc2[j]);
        op[(size_t)(obase + j)*HW] = lo + hi + b_off[obase + j];
    }
}

// ============================================================
// Kernel 3: deformable conv + ReLU
// block: 128 thr, tile = 32 pixels x 128 couts
// micro-GEMM in packed f32x2 (pixel pairs)
// ============================================================
__global__ __launch_bounds__(128, 8) void main_kernel(
        const float* __restrict__ x,
        float* __restrict__ out) {
    __shared__ __align__(16) float s[32][36];     // sampled vals [c][px]
    __shared__ __align__(16) float ws[4224];      // w slice [c][co] (4096) / epi [128][33]

    int b  = blockIdx.z;
    int h  = blockIdx.y;
    int w0 = blockIdx.x * 32;
    int t  = threadIdx.x;
    int lane = t & 31, wid = t >> 5;

    // acc2[co][px-pair]: pixels (px8+2p, px8+2p+1) packed in one u64
    unsigned long long acc2[4][4];
    #pragma unroll
    for (int i = 0; i < 4; i++)
        #pragma unroll
        for (int p = 0; p < 4; p++) acc2[i][p] = 0ULL;

    const float* xb   = x + (size_t)b*CIN*HW;
    const float* offp = g_off + (size_t)b*NOFF*HW + h*W_ + w0 + lane;

    int co4 = lane * 4;   // compute-phase: 4 consecutive couts
    int px8 = wid * 8;    // compute-phase: 8 consecutive pixels

    for (int g = 0; g < G_; g++) {
        const float* xg = xb + (size_t)g*CG*HW;
        for (int kk = 0; kk < KK; kk++) {
            __syncthreads();   // protect smem from previous compute reads

            // ---- stage weight slice [c][co] (coalesced float4) ----
            const float4* wtp = (const float4*)(g_wT + (size_t)(g*9 + kk)*CG*COUT);
            float4* wsd = (float4*)ws;
            #pragma unroll
            for (int i = 0; i < 8; i++) wsd[t + i*128] = wtp[t + i*128];

            // ---- per-pixel sampling params (px = lane) ----
            float offy = offp[(size_t)((g*9 + kk)*2 + 0)*HW];
            float offx = offp[(size_t)((g*9 + kk)*2 + 1)*HW];
            int ky = kk / 3, kx = kk % 3;
            float py  = offy + (float)(ky - 1) + (float)h;
            float pxf = offx + (float)(kx - 1) + (float)(w0 + lane);
            float y0f = floorf(py), x0f = floorf(pxf);
            float wy1 = py - y0f, wx1 = pxf - x0f;
            float wy0 = 1.f - wy1, wx0 = 1.f - wx1;
            int y0 = (int)y0f, x0 = (int)x0f;
            int y1 = y0 + 1,  x1 = x0 + 1;
            bool vy0 = (y0 >= 0) & (y0 < H_);
            bool vy1 = (y1 >= 0) & (y1 < H_);
            bool vx0 = (x0 >= 0) & (x0 < W_);
            bool vx1 = (x1 >= 0) & (x1 < W_);
            float c00 = (vy0 & vx0) ? wy0*wx0 : 0.f;
            float c01 = (vy0 & vx1) ? wy0*wx1 : 0.f;
            float c10 = (vy1 & vx0) ? wy1*wx0 : 0.f;
            float c11 = (vy1 & vx1) ? wy1*wx1 : 0.f;
            int iy0 = min(max(y0, 0), H_-1), iy1 = min(max(y1, 0), H_-1);
            int ix0 = min(max(x0, 0), W_-1), ix1 = min(max(x1, 0), W_-1);
            int i00 = iy0*W_ + ix0, i01 = iy0*W_ + ix1;
            int i10 = iy1*W_ + ix0, i11 = iy1*W_ + ix1;

            // ---- bilinear gather: thread does 8 channel rows of s ----
            #pragma unroll
            for (int j = 0; j < 8; j++) {
                const float* xc = xg + (size_t)(wid + 4*j)*HW;
                float v = c00*xc[i00] + c01*xc[i01] + c10*xc[i10] + c11*xc[i11];
                s[wid + 4*j][lane] = v;
            }
            __syncthreads();

            // ---- micro-GEMM (f32x2): acc2[4co][4 px-pairs] += w[c][co]*s[c][px] ----
            #pragma unroll 8
            for (int c = 0; c < CG; c++) {
                float4 wq = *(const float4*)&ws[c*128 + co4];
                unsigned long long wd0 = pack2(wq.x);
                unsigned long long wd1 = pack2(wq.y);
                unsigned long long wd2 = pack2(wq.z);
                unsigned long long wd3 = pack2(wq.w);
                const unsigned long long* sp = (const unsigned long long*)&s[c][px8];
                unsigned long long s0 = sp[0], s1 = sp[1], s2 = sp[2], s3 = sp[3];
                ffma2(acc2[0][0], wd0, s0); ffma2(acc2[0][1], wd0, s1);
                ffma2(acc2[0][2], wd0, s2); ffma2(acc2[0][3], wd0, s3);
                ffma2(acc2[1][0], wd1, s0); ffma2(acc2[1][1], wd1, s1);
                ffma2(acc2[1][2], wd1, s2); ffma2(acc2[1][3], wd1, s3);
                ffma2(acc2[2][0], wd2, s0); ffma2(acc2[2][1], wd2, s1);
                ffma2(acc2[2][2], wd2, s2); ffma2(acc2[2][3], wd2, s3);
                ffma2(acc2[3][0], wd3, s0); ffma2(acc2[3][1], wd3, s1);
                ffma2(acc2[3][2], wd3, s2); ffma2(acc2[3][3], wd3, s3);
            }
        }
    }

    // ---- epilogue: transpose via smem, ReLU, coalesced NCHW store ----
    __syncthreads();
    float* s2 = ws;   // reuse as [128][33]
    #pragma unroll
    for (int i = 0; i < 4; i++)
        #pragma unroll
        for (int p = 0; p < 4; p++) {
            float lo, hi;
            unpack2(lo, hi, acc2[i][p]);
            s2[(co4 + i)*33 + (px8 + 2*p)]     = lo > 0.f ? lo : 0.f;
            s2[(co4 + i)*33 + (px8 + 2*p + 1)] = hi > 0.f ? hi : 0.f;
        }
    __syncthreads();
    float* outp = out + (size_t)b*COUT*HW + h*W_ + w0;
    #pragma unroll
    for (int k = 0; k < 32; k++) {
        int row = wid*32 + k;
        outp[(size_t)row*HW + lane] = s2[row*33 + lane];
    }
}

// ============================================================
extern "C" void kernel_launch(void* const* d_in, const int* in_sizes, int n_in,
                              void* d_out, int out_size) {
    const float* x     = (const float*)d_in[0];
    const float* w_off = (const float*)d_in[1];
    const float* b_off = (const float*)d_in[2];
    const float* w_def = (const float*)d_in[3];
    float* out = (float*)d_out;

    prep_w<<<576, 256>>>(w_def);
    off_kernel<<<dim3(W_/32, H_, B_), 256>>>(x, w_off, b_off);
    main_kernel<<<dim3(W_/32, H_, B_), 128>>>(x, out);
}

// round 11
// speedup vs baseline: 1.3351x; 1.3082x over previous
#include <cuda_runtime.h>
#include <cuda_bf16.h>
#include <mma.h>
#include <cstdint>

using namespace nvcuda;

#define B_   4
#define CIN  128
#define COUT 128
#define H_   128
#define W_   128
#define G_   4
#define CG   32
#define KK   9
#define HW   (H_*W_)
#define NOFF 72   // G*KK*2
#define NTILE 36  // G*KK
#define KDIM 96   // split-K per tile: 32 w_hi|s_hi + 32 w_hi|s_lo + 32 w_lo|s_hi
#define ASTR 104  // A smem ldm (bf16 elems): 208B rows, 16B-aligned
#define BSTR 136  // B smem ldm (bf16 elems): 272B rows, 16B-aligned

// ---- scratch (device globals; no allocations allowed) ----
__device__ float g_off[B_*NOFF*HW];                          // 18 MB offset map [b][o][h][w]
__device__ __align__(16) __nv_bfloat16 g_wA[NTILE*128*KDIM]; // 884 KB: A tiles [gk][co][k]

// ============================================================
// Kernel 1: build A weight tiles [gk][co][k], k in [0,96):
//   k  0-31: w_hi(c=k)     (pairs with s_hi)
//   k 32-63: w_hi(c=k-32)  (pairs with s_lo)
//   k 64-95: w_lo(c=k-64)  (pairs with s_hi)
// ============================================================
__global__ void prep_w(const float* __restrict__ w_def) {
    int i = blockIdx.x * 256 + threadIdx.x;      // over 36*128*96
    if (i >= NTILE * 128 * KDIM) return;
    int k  = i % KDIM;
    int co = (i / KDIM) & 127;
    int gk = i / (KDIM * 128);
    int g = gk / 9, kk = gk % 9;
    int c = k & 31;

    float w = w_def[(co * CIN + g * CG + c) * KK + kk];
    __nv_bfloat16 hi = __float2bfloat16(w);
    __nv_bfloat16 v = (k < 64) ? hi : __float2bfloat16(w - __bfloat162float(hi));
    g_wA[i] = v;
}

// ============================================================
// Kernel 2: 1x1 offset conv (fp32 path; known-good R3 form)
// ============================================================
__global__ __launch_bounds__(256) void off_kernel(
        const float* __restrict__ x,
        const float* __restrict__ w_off,
        const float* __restrict__ b_off) {
    __shared__ __align__(16) float xs[32][132];   // 528B rows: float4-legal
    __shared__ __align__(16) float ws[NOFF][32];

    int b = blockIdx.z, h = blockIdx.y, w0 = blockIdx.x * 32;
    int t = threadIdx.x, lane = t & 31, wid = t >> 5;

    const float* xp = x + (size_t)b*CIN*HW + h*W_ + w0;
    for (int i = t; i < 128*32; i += 256) {
        int c = i >> 5, px = i & 31;
        xs[px][c] = xp[(size_t)c*HW + px];
    }

    float acc[9];
    #pragma unroll
    for (int j = 0; j < 9; j++) acc[j] = 0.f;
    int obase = wid * 9;

    for (int cc = 0; cc < 4; cc++) {
        __syncthreads();
        for (int i = t; i < NOFF*32; i += 256) {
            int o = i >> 5, c2 = i & 31;
            ws[o][c2] = w_off[o*CIN + cc*32 + c2];
        }
        __syncthreads();
        #pragma unroll
        for (int c2 = 0; c2 < 32; c2 += 4) {
            float4 xv = *(const float4*)&xs[lane][cc*32 + c2];
            #pragma unroll
            for (int j = 0; j < 9; j++) {
                float4 wq = *(const float4*)&ws[obase + j][c2];
                acc[j] += xv.x*wq.x + xv.y*wq.y + xv.z*wq.z + xv.w*wq.w;
            }
        }
    }
    float* op = g_off + (size_t)b*NOFF*HW + h*W_ + w0 + lane;
    #pragma unroll
    for (int j = 0; j < 9; j++)
        op[(size_t)(obase + j)*HW] = acc[j] + b_off[obase + j];
}

// ============================================================
// Kernel 3: deformable conv + ReLU via WMMA bf16 split-MMA
// block 256 thr (8 warps), tile = 1 row (128 px) x 128 cout
// warp tile: 64 co x 32 px = 4x2 wmma 16x16x16 tiles
// ============================================================
__global__ __launch_bounds__(256, 2) void main_kernel(
        const float* __restrict__ x,
        float* __restrict__ out) {
    __shared__ __align__(16) __nv_bfloat16 As[128 * ASTR];  // 26624 B
    __shared__ __align__(16) __nv_bfloat16 Bs[64 * BSTR];   // 17408 B

    int t = threadIdx.x, lane = t & 31, wid = t >> 5;
    int h = blockIdx.x, b = blockIdx.y;

    // warp tiling
    int warp_m = wid & 1;          // 0,1 -> co halves
    int warp_n = wid >> 1;         // 0..3 -> 32-px strips
    int co_base = warp_m * 64;
    int npx0 = warp_n * 32;

    // gather mapping
    int px = (wid & 3) * 32 + lane;     // 0..127
    int cbase = (wid >> 2) * 16;        // 0 or 16

    wmma::fragment<wmma::accumulator, 16, 16, 16, float> acc[4][2];
    #pragma unroll
    for (int mt = 0; mt < 4; mt++)
        #pragma unroll
        for (int nt = 0; nt < 2; nt++)
            wmma::fill_fragment(acc[mt][nt], 0.f);

    const float* xb = x + (size_t)b*CIN*HW;
    const float* offp = g_off + (size_t)b*NOFF*HW + h*W_ + px;

    for (int gk = 0; gk < NTILE; gk++) {
        int g = gk / 9, kk = gk % 9;
        __syncthreads();   // previous iteration's fragment loads complete

        // ---- stage A tile: [128 co][96 k] -> padded rows ----
        {
            const float4* src = (const float4*)(g_wA + (size_t)gk * (128*KDIM));
            for (int i = t; i < 1536; i += 256) {
                int row = i / 12, q = i - row * 12;
                *(float4*)((char*)As + row * (ASTR*2) + q * 16) = src[i];
            }
        }

        // ---- gather B tile: rows 0-31 s_hi, rows 32-63 s_lo ----
        float offy = offp[(size_t)(gk*2 + 0)*HW];
        float offx = offp[(size_t)(gk*2 + 1)*HW];
        int ky = kk / 3, kx = kk % 3;
        float py  = offy + (float)(ky - 1) + (float)h;
        float pxf = offx + (float)(kx - 1) + (float)px;
        float y0f = floorf(py), x0f = floorf(pxf);
        float wy1 = py - y0f, wx1 = pxf - x0f;
        float wy0 = 1.f - wy1, wx0 = 1.f - wx1;
        int y0 = (int)y0f, x0 = (int)x0f;
        int y1 = y0 + 1, x1 = x0 + 1;
        bool vy0 = (y0 >= 0) & (y0 < H_);
        bool vy1 = (y1 >= 0) & (y1 < H_);
        bool vx0 = (x0 >= 0) & (x0 < W_);
        bool vx1 = (x1 >= 0) & (x1 < W_);
        float c00 = (vy0 & vx0) ? wy0*wx0 : 0.f;
        float c01 = (vy0 & vx1) ? wy0*wx1 : 0.f;
        float c10 = (vy1 & vx0) ? wy1*wx0 : 0.f;
        float c11 = (vy1 & vx1) ? wy1*wx1 : 0.f;
        int iy0 = min(max(y0, 0), H_-1), iy1 = min(max(y1, 0), H_-1);
        int ix0 = min(max(x0, 0), W_-1), ix1 = min(max(x1, 0), W_-1);
        int i00 = iy0*W_ + ix0, i01 = iy0*W_ + ix1;
        int i10 = iy1*W_ + ix0, i11 = iy1*W_ + ix1;

        const float* xg = xb + (size_t)g*CG*HW;
        #pragma unroll
        for (int j = 0; j < 16; j++) {
            int c = cbase + j;
            const float* xc = xg + (size_t)c*HW;
            float v = c00*xc[i00] + c01*xc[i01] + c10*xc[i10] + c11*xc[i11];
            __nv_bfloat16 hb = __float2bfloat16(v);
            __nv_bfloat16 lb = __float2bfloat16(v - __bfloat162float(hb));
            Bs[c*BSTR + px] = hb;          // s_hi rows [0,32)
            Bs[(32 + c)*BSTR + px] = lb;   // s_lo rows [32,64)
        }
        __syncthreads();

        // ---- 6 k16-steps; steps 4,5 reuse s_hi rows against w_lo cols ----
        #pragma unroll
        for (int kb = 0; kb < 6; kb++) {
            int krow = (kb & 3) * 16;      // 0,16,32,48,0,16
            wmma::fragment<wmma::matrix_b, 16, 16, 16, __nv_bfloat16, wmma::row_major> bf[2];
            #pragma unroll
            for (int nt = 0; nt < 2; nt++)
                wmma::load_matrix_sync(bf[nt], Bs + krow*BSTR + npx0 + nt*16, BSTR);
            #pragma unroll
            for (int mt = 0; mt < 4; mt++) {
                wmma::fragment<wmma::matrix_a, 16, 16, 16, __nv_bfloat16, wmma::row_major> af;
                wmma::load_matrix_sync(af, As + (co_base + mt*16)*ASTR + kb*16, ASTR);
                #pragma unroll
                for (int nt = 0; nt < 2; nt++)
                    wmma::mma_sync(acc[mt][nt], af, bf[nt], acc[mt][nt]);
            }
        }
    }

    // ---- epilogue: fragment ReLU + direct wmma store to gmem ----
    float* outp = out + (size_t)b*COUT*HW + h*W_;
    #pragma unroll
    for (int mt = 0; mt < 4; mt++)
        #pragma unroll
        for (int nt = 0; nt < 2; nt++) {
            #pragma unroll
            for (int e = 0; e < acc[mt][nt].num_elements; e++)
                acc[mt][nt].x[e] = fmaxf(acc[mt][nt].x[e], 0.f);
            wmma::store_matrix_sync(outp + (size_t)(co_base + mt*16)*HW + npx0 + nt*16,
                                    acc[mt][nt], HW, wmma::mem_row_major);
        }
}

// ============================================================
extern "C" void kernel_launch(void* const* d_in, const int* in_sizes, int n_in,
                              void* d_out, int out_size) {
    const float* x     = (const float*)d_in[0];
    const float* w_off = (const float*)d_in[1];
    const float* b_off = (const float*)d_in[2];
    const float* w_def = (const float*)d_in[3];
    float* out = (float*)d_out;

    prep_w<<<(NTILE*128*KDIM + 255)/256, 256>>>(w_def);
    off_kernel<<<dim3(W_/32, H_, B_), 256>>>(x, w_off, b_off);
    main_kernel<<<dim3(H_, B_), 256>>>(x, out);
}